// round 17
// baseline (speedup 1.0000x reference)
#include <cuda_runtime.h>
#include <cuda_fp16.h>
#include <math.h>
#include <stdint.h>

#define N_TOK 4096
#define DIM   1024
#define HID   768
#define NE    23
#define TOPK  3
#define NSLOT (N_TOK * TOPK)

#define TBM 128
#define TBN 128
#define TBK 32
#define A_STRIDE 80
#define B_STRIDE 272
#define A_STG   10240
#define NSTAGE_A 4
#define B_OFF   (NSTAGE_A * A_STG)
#define B_STG   8704
#define EPI_SZ  (128 * 132 * 4)
#define SMEM_SZ EPI_SZ

#define GATE_TPB 8
#define GATE_NB  (N_TOK / GATE_TPB)
#define GATE_SMEM ((DIM * NE + GATE_TPB * DIM) * 4)

// ---------------- scratch ----------------
__device__ int   g_counts[NE];
__device__ int   g_list[(size_t)NE * N_TOK];
__device__ float g_tw[NSLOT];
__device__ float g_partial[GATE_NB * NE];
__device__ __half g_Yrh[(size_t)NSLOT * DIM];   // routed MLP2 out (fp16, *tw)
__device__ __half g_Ysh[(size_t)N_TOK * DIM];   // shared MLP2 out (fp16)

__device__ __half g_xh[(size_t)N_TOK * DIM];
__device__ __half g_Hsh[(size_t)N_TOK * HID];
__device__ __half g_Hrh[(size_t)NSLOT * HID];

__device__ __forceinline__ float gelu_exact(float v) {
    return 0.5f * v * (1.0f + erff(v * 0.7071067811865476f));
}
__device__ __forceinline__ uint32_t smem_u32(const void* p) {
    uint32_t a;
    asm("{ .reg .u64 t; cvta.to.shared.u64 t, %1; cvt.u32.u64 %0, t; }" : "=r"(a) : "l"(p));
    return a;
}
__device__ __forceinline__ void ldsm_x4(uint32_t addr, uint32_t* r) {
    asm volatile("ldmatrix.sync.aligned.m8n8.x4.shared.b16 {%0,%1,%2,%3}, [%4];"
                 : "=r"(r[0]), "=r"(r[1]), "=r"(r[2]), "=r"(r[3]) : "r"(addr));
}
__device__ __forceinline__ void ldsm_x4_t(uint32_t addr, uint32_t* r) {
    asm volatile("ldmatrix.sync.aligned.m8n8.x4.trans.shared.b16 {%0,%1,%2,%3}, [%4];"
                 : "=r"(r[0]), "=r"(r[1]), "=r"(r[2]), "=r"(r[3]) : "r"(addr));
}
__device__ __forceinline__ void mma_f16(float* c, const uint32_t* a, uint32_t b0, uint32_t b1) {
    asm volatile("mma.sync.aligned.m16n8k16.row.col.f32.f16.f16.f32 "
                 "{%0,%1,%2,%3}, {%4,%5,%6,%7}, {%8,%9}, {%0,%1,%2,%3};"
                 : "+f"(c[0]), "+f"(c[1]), "+f"(c[2]), "+f"(c[3])
                 : "r"(a[0]), "r"(a[1]), "r"(a[2]), "r"(a[3]), "r"(b0), "r"(b1));
}
__device__ __forceinline__ void cpa16(uint32_t dst, const void* src) {
    asm volatile("cp.async.cg.shared.global [%0], [%1], 16;" :: "r"(dst), "l"(src));
}
__device__ __forceinline__ void cpa_commit() {
    asm volatile("cp.async.commit_group;");
}
template<int N> __device__ __forceinline__ void cpa_wait() {
    asm volatile("cp.async.wait_group %0;" :: "n"(N));
}
__device__ __forceinline__ uint32_t pack2h(__half a, __half b) {
    return (uint32_t)__half_as_ushort(a) | ((uint32_t)__half_as_ushort(b) << 16);
}
__device__ __forceinline__ uint32_t cvt2h(float a, float b) {
    return pack2h(__float2half_rn(a), __float2half_rn(b));
}

// ---------------- init: zero expert counters ----------------
__global__ void init_kernel() {
    if (threadIdx.x < NE) g_counts[threadIdx.x] = 0;
}

// ---------------- gate: 8 tokens/block; also emits xh and aux partials ----------------
__global__ void __launch_bounds__(256) gate8_kernel(
    const float* __restrict__ x,
    const float* __restrict__ gW,
    const float* __restrict__ gb,
    const float* __restrict__ rbias)
{
    extern __shared__ float dyn[];
    float* gWs = dyn;
    float* xs  = dyn + DIM * NE;
    __shared__ float gv[GATE_TPB][NE];
    __shared__ float gvn[GATE_TPB][NE];

    int t = threadIdx.x;
    const float4* gWv = (const float4*)gW;
    for (int i = t; i < DIM * NE / 4; i += 256) ((float4*)gWs)[i] = gWv[i];
    const float4* xv = (const float4*)(x + (size_t)blockIdx.x * GATE_TPB * DIM);
    for (int i = t; i < GATE_TPB * DIM / 4; i += 256) ((float4*)xs)[i] = xv[i];
    __syncthreads();

    {
        uint2* xhv = (uint2*)(g_xh + (size_t)blockIdx.x * GATE_TPB * DIM);
        for (int i = t; i < GATE_TPB * DIM / 4; i += 256) {
            float4 v = ((float4*)xs)[i];
            xhv[i] = make_uint2(cvt2h(v.x, v.y), cvt2h(v.z, v.w));
        }
    }

    int w = t >> 5;
    int l = t & 31;
    int n = blockIdx.x * GATE_TPB + w;

    if (l < NE) {
        const float* xrow = xs + w * DIM;
        float acc = 0.f;
        #pragma unroll 8
        for (int i = 0; i < DIM; i++)
            acc += xrow[i] * gWs[i * NE + l];
        gv[w][l] = 1.0f / (1.0f + expf(-(acc + gb[l])));
    }
    __syncwarp();

    float gsum = 0.f;
    #pragma unroll
    for (int q = 0; q < NE; q++) gsum += gv[w][q];
    if (l < NE) gvn[w][l] = gv[w][l] / gsum;

    if (l == 0) {
        int   idx[TOPK];
        float wv[TOPK];
        unsigned used = 0;
        for (int k = 0; k < TOPK; k++) {
            float best = -1e30f; int bi = 0;
            for (int q = 0; q < NE; q++) {
                if (used & (1u << q)) continue;
                float s = gv[w][q] + rbias[q];
                if (s > best) { best = s; bi = q; }
            }
            used |= (1u << bi);
            idx[k] = bi;
            wv[k]  = gv[w][bi];
        }
        float ws = wv[0] + wv[1] + wv[2];
        for (int k = 0; k < TOPK; k++) {
            int slot = n * TOPK + k;
            g_tw[slot] = wv[k] / ws;
            int pos = atomicAdd(&g_counts[idx[k]], 1);
            g_list[(size_t)idx[k] * N_TOK + pos] = slot;
        }
    }
    __syncthreads();

    if (t < NE) {
        float s = 0.f;
        #pragma unroll
        for (int r = 0; r < GATE_TPB; r++) s += gvn[r][t];
        g_partial[blockIdx.x * NE + t] = s;
    }
}

// ---------------- fp16 GEMM (R14/R16 config) ----------------
// MLP1P: gelu(D+bias) -> fp16 (OutRH/OutSH)
// else : routed (D+bias)*tw -> fp16 OutRH ; shared (D+bias) -> fp16 OutSH
template<int KDIM, int NOUT, bool MLP1P>
__global__ void __launch_bounds__(256, 2) mma_mlp(
    const __half* __restrict__ ArH, const __half* __restrict__ AsH,
    const float* __restrict__ BrF, const float* __restrict__ BsF,
    const float* __restrict__ biasR, const float* __restrict__ biasS,
    __half* __restrict__ OutRH, __half* __restrict__ OutSH)
{
    constexpr int NC = KDIM / TBK;

    int ez = blockIdx.z;
    bool sh = (ez == NE);
    int cnt = sh ? N_TOK : g_counts[ez];
    int m0  = blockIdx.x * TBM;
    if (m0 >= cnt) return;
    int n0  = blockIdx.y * TBN;

    extern __shared__ char smem[];
    uint32_t sbase = smem_u32(smem);

    int tid  = threadIdx.x;
    int wid  = tid >> 5;
    int lane = tid & 31;
    int wm   = wid >> 2;
    int wn   = wid & 3;

    const __half* AH  = sh ? AsH : ArH;
    const float*  BF  = sh ? BsF : (BrF + (size_t)ez * KDIM * NOUT);
    const float* bias = sh ? biasS : (biasR + (size_t)ez * NOUT);

    int arow = tid >> 1;
    int au   = tid & 1;
    int gi_a = m0 + arow;
    int grow;
    if (sh) {
        grow = gi_a;
    } else {
        int gg   = (gi_a < cnt) ? gi_a : (cnt - 1);
        int slot = g_list[(size_t)ez * N_TOK + gg];
        grow = MLP1P ? (slot / TOPK) : slot;
    }
    const __half* ApH = AH + (size_t)grow * KDIM + au * 16;
    uint32_t aoff = (uint32_t)(arow * A_STRIDE + au * 32);

    auto issue_A = [&](int c, int st) {
        uint32_t sA = sbase + (uint32_t)(st * A_STG);
        int k0 = c * TBK;
        cpa16(sA + aoff,      ApH + k0);
        cpa16(sA + aoff + 16, ApH + k0 + 8);
        cpa_commit();
    };

    int bk = tid >> 3;
    int bc = tid & 7;
    const float* BpF = BF + (size_t)bk * NOUT + n0 + bc * 8;
    uint32_t boff = (uint32_t)(bk * B_STRIDE + bc * 16);

    float4 fb[4];
    auto load_B = [&](int c) {
        size_t k0n = (size_t)(c * TBK) * NOUT;
        fb[0] = *(const float4*)(BpF + k0n);
        fb[1] = *(const float4*)(BpF + k0n + 4);
        fb[2] = *(const float4*)(BpF + k0n + 64);
        fb[3] = *(const float4*)(BpF + k0n + 68);
    };
    auto store_B = [&](int bs) {
        char* dst = smem + B_OFF + bs * B_STG;
        uint4 v0, v1;
        v0.x = cvt2h(fb[0].x, fb[0].y); v0.y = cvt2h(fb[0].z, fb[0].w);
        v0.z = cvt2h(fb[1].x, fb[1].y); v0.w = cvt2h(fb[1].z, fb[1].w);
        v1.x = cvt2h(fb[2].x, fb[2].y); v1.y = cvt2h(fb[2].z, fb[2].w);
        v1.z = cvt2h(fb[3].x, fb[3].y); v1.w = cvt2h(fb[3].z, fb[3].w);
        *(uint4*)(dst + boff)       = v0;
        *(uint4*)(dst + boff + 128) = v1;
    };

    issue_A(0, 0);
    if (NC > 1) issue_A(1, 1);
    if (NC > 2) issue_A(2, 2);
    load_B(0);
    store_B(0);
    if (NC > 1) load_B(1);

    float acc[4][4][4];
    #pragma unroll
    for (int i = 0; i < 4; i++)
        #pragma unroll
        for (int j = 0; j < 4; j++)
            #pragma unroll
            for (int q = 0; q < 4; q++) acc[i][j][q] = 0.f;

    uint32_t aAddr = sbase + (uint32_t)((wm * 64 + (lane & 15)) * A_STRIDE + ((lane >> 4) << 4));
    uint32_t bAddr = sbase + B_OFF + (uint32_t)((lane & 15) * B_STRIDE + ((wn * 32 + (lane >> 4) * 8) << 1));

    int st = 0;
    for (int c = 0; c < NC; c++) {
        if (c + 3 <= NC)      cpa_wait<2>();
        else if (c + 2 == NC) cpa_wait<1>();
        else                  cpa_wait<0>();
        __syncthreads();
        if (c + 3 < NC) {
            int st3 = st + 3; if (st3 >= NSTAGE_A) st3 -= NSTAGE_A;
            issue_A(c + 3, st3);
        }
        if (c + 1 < NC) {
            store_B((c + 1) & 1);
            if (c + 2 < NC) load_B(c + 2);
        }
        uint32_t aS = aAddr + (uint32_t)(st * A_STG);
        uint32_t bS = bAddr + (uint32_t)((c & 1) * B_STG);
        #pragma unroll
        for (int ks = 0; ks < 2; ks++) {
            uint32_t ahF[4][4];
            #pragma unroll
            for (int i = 0; i < 4; i++)
                ldsm_x4(aS + ks * 32 + i * (16 * A_STRIDE), ahF[i]);
            uint32_t bhF[2][4];
            #pragma unroll
            for (int g = 0; g < 2; g++)
                ldsm_x4_t(bS + ks * (16 * B_STRIDE) + g * 32, bhF[g]);
            #pragma unroll
            for (int i = 0; i < 4; i++) {
                #pragma unroll
                for (int j = 0; j < 4; j++) {
                    int g = j >> 1, o = (j & 1) * 2;
                    mma_f16(acc[i][j], ahF[i], bhF[g][o], bhF[g][o + 1]);
                }
            }
        }
        if (++st == NSTAGE_A) st = 0;
    }
    __syncthreads();

    float* epi = (float*)smem;
    {
        int rb = wm * 64 + (lane >> 2);
        int cb = wn * 32 + (lane & 3) * 2;
        #pragma unroll
        for (int i = 0; i < 4; i++) {
            #pragma unroll
            for (int j = 0; j < 4; j++) {
                int r = rb + i * 16;
                int cc = cb + j * 8;
                epi[r * 132 + cc]           = acc[i][j][0];
                epi[r * 132 + cc + 1]       = acc[i][j][1];
                epi[(r + 8) * 132 + cc]     = acc[i][j][2];
                epi[(r + 8) * 132 + cc + 1] = acc[i][j][3];
            }
        }
    }
    __syncthreads();

    for (int i = tid; i < TBM * (TBN / 4); i += 256) {
        int r  = i >> 5;
        int c4 = i & 31;
        int gi = m0 + r;
        if (gi >= cnt) continue;
        float4 v = *(float4*)&epi[r * 132 + c4 * 4];
        int col = n0 + c4 * 4;
        float4 b4 = *(const float4*)(bias + col);
        v.x += b4.x; v.y += b4.y; v.z += b4.z; v.w += b4.w;
        if (MLP1P) {
            v.x = gelu_exact(v.x); v.y = gelu_exact(v.y);
            v.z = gelu_exact(v.z); v.w = gelu_exact(v.w);
        }
        size_t orow;
        __half* OH;
        if (sh) {
            orow = (size_t)gi; OH = OutSH;
        } else {
            int slot = g_list[(size_t)ez * N_TOK + gi];
            orow = (size_t)slot; OH = OutRH;
            if (!MLP1P) {
                float w = g_tw[slot];
                v.x *= w; v.y *= w; v.z *= w; v.w *= w;
            }
        }
        uint2 h;
        h.x = cvt2h(v.x, v.y);
        h.y = cvt2h(v.z, v.w);
        *(uint2*)(OH + orow * NOUT + col) = h;
    }
}

// ---------------- combine: out = Ysh + sum_k Yrh  (8 elems/thread; + aux in block 0) ----------------
__global__ void combine_kernel(float* __restrict__ out, int out_size)
{
    __shared__ float Ps[32];
    if (blockIdx.x == 0) {
        int t = threadIdx.x;
        if (t < NE) {
            float s = 0.f;
            for (int b = 0; b < GATE_NB; b++) s += g_partial[b * NE + t];
            Ps[t] = s;
        }
        __syncthreads();
        if (t == 0 && out_size > N_TOK * DIM) {
            float aux = 0.f;
            for (int e = 0; e < NE; e++) {
                float P = Ps[e] / (float)N_TOK;
                float F = ((float)NE * (float)g_counts[e]) / ((float)TOPK * (float)N_TOK);
                aux += P * F;
            }
            out[(size_t)N_TOK * DIM] = aux;
        }
    }
    int idx = blockIdx.x * blockDim.x + threadIdx.x;   // over N_TOK*DIM/8
    if (idx >= N_TOK * (DIM / 8)) return;
    int n  = idx / (DIM / 8);
    int d8 = idx % (DIM / 8);

    float s[8];
    {
        uint4 ys = __ldg(&((const uint4*)g_Ysh)[(size_t)n * (DIM / 8) + d8]);
        __half2 h0 = *(__half2*)&ys.x, h1 = *(__half2*)&ys.y;
        __half2 h2 = *(__half2*)&ys.z, h3 = *(__half2*)&ys.w;
        s[0] = __low2float(h0); s[1] = __high2float(h0);
        s[2] = __low2float(h1); s[3] = __high2float(h1);
        s[4] = __low2float(h2); s[5] = __high2float(h2);
        s[6] = __low2float(h3); s[7] = __high2float(h3);
    }
    #pragma unroll
    for (int k = 0; k < TOPK; k++) {
        uint4 y = __ldg(&((const uint4*)g_Yrh)[(size_t)(n * TOPK + k) * (DIM / 8) + d8]);
        __half2 h0 = *(__half2*)&y.x, h1 = *(__half2*)&y.y;
        __half2 h2 = *(__half2*)&y.z, h3 = *(__half2*)&y.w;
        s[0] += __low2float(h0); s[1] += __high2float(h0);
        s[2] += __low2float(h1); s[3] += __high2float(h1);
        s[4] += __low2float(h2); s[5] += __high2float(h2);
        s[6] += __low2float(h3); s[7] += __high2float(h3);
    }
    float4* o = (float4*)(out + (size_t)n * DIM + d8 * 8);
    o[0] = make_float4(s[0], s[1], s[2], s[3]);
    o[1] = make_float4(s[4], s[5], s[6], s[7]);
}

// ---------------- launch ----------------
extern "C" void kernel_launch(void* const* d_in, const int* in_sizes, int n_in,
                              void* d_out, int out_size)
{
    const float* x   = (const float*)d_in[0];
    const float* gW  = (const float*)d_in[1];
    const float* gb  = (const float*)d_in[2];
    const float* rb  = (const float*)d_in[3];
    const float* W1  = (const float*)d_in[4];
    const float* b1  = (const float*)d_in[5];
    const float* W2  = (const float*)d_in[6];
    const float* b2  = (const float*)d_in[7];
    const float* sW1 = (const float*)d_in[8];
    const float* sb1 = (const float*)d_in[9];
    const float* sW2 = (const float*)d_in[10];
    const float* sb2 = (const float*)d_in[11];
    float* out = (float*)d_out;

    void* p;
    cudaGetSymbolAddress(&p, g_xh);   __half* xh   = (__half*)p;
    cudaGetSymbolAddress(&p, g_Hsh);  __half* Hsh  = (__half*)p;
    cudaGetSymbolAddress(&p, g_Hrh);  __half* Hrh  = (__half*)p;
    cudaGetSymbolAddress(&p, g_Yrh);  __half* Yrh  = (__half*)p;
    cudaGetSymbolAddress(&p, g_Ysh);  __half* Ysh  = (__half*)p;

    cudaFuncSetAttribute(mma_mlp<DIM, HID, true >, cudaFuncAttributeMaxDynamicSharedMemorySize, SMEM_SZ);
    cudaFuncSetAttribute(mma_mlp<HID, DIM, false>, cudaFuncAttributeMaxDynamicSharedMemorySize, SMEM_SZ);
    cudaFuncSetAttribute(gate8_kernel, cudaFuncAttributeMaxDynamicSharedMemorySize, GATE_SMEM);

    init_kernel<<<1, 32>>>();                                                          // 0
    gate8_kernel<<<GATE_NB, 256, GATE_SMEM>>>(x, gW, gb, rb);                          // 1

    // 2: MLP1: x -> Hr (slots, gelu fp16), Hs (tokens, gelu fp16)
    mma_mlp<DIM, HID, true ><<<dim3(N_TOK / TBM, HID / TBN, NE + 1), 256, SMEM_SZ>>>(
        xh, xh, W1, sW1, b1, sb1, Hrh, Hsh);
    // 3: MLP2: Hr -> Yrh (*tw fp16), Hs -> Ysh (fp16)
    mma_mlp<HID, DIM, false><<<dim3(N_TOK / TBM, DIM / TBN, NE + 1), 256, SMEM_SZ>>>(
        Hrh, Hsh, W2, sW2, b2, sb2, Yrh, Ysh);

    combine_kernel<<<(N_TOK * (DIM / 8) + 255) / 256, 256>>>(out, out_size);           // 4
}